// round 8
// baseline (speedup 1.0000x reference)
#include <cuda_runtime.h>
#include <cuda_bf16.h>
#include <cstdint>

#define NU 70000
#define NI 30000
#define NN 100000   // NU+NI
#define RR 3
#define DD 64
#define EE 1600000
#define CAP 64                 // bucket capacity per (rel,row)

// output layout (f32, flattened tuple)
#define OFF_U   ((size_t)0)
#define OFF_I   ((size_t)NU*192)                    // 13,440,000
#define OFF_RELA (OFF_I + (size_t)(NI+1)*192)       // 19,200,192
#define OFF_S1  (OFF_RELA + 192)                    // 19,200,384
#define OFF_S2  (OFF_S1 + NU)                       // 19,270,384

// -------- scratch (device globals; no allocation allowed) --------
__device__ float g_ego [(size_t)NN*RR*DD];
__device__ float g_all [(size_t)NN*RR*DD];
__device__ float g_rela[3*RR*DD];   // rela[0..2], each 3x64
__device__ int   g_cnt [RR*NN];
__device__ __align__(16) int2 g_bkt[(size_t)RR*NN*CAP];   // zero-init; unwritten slots stay (0, 0.0f)

__device__ __forceinline__ float lrelu(float x){ return x > 0.f ? x : 0.01f*x; }

// ---------------- rela chain + rela_out + i_emb pad row ----------------
__global__ void k_rela(const float* __restrict__ rel_emb,
                       const float* __restrict__ Wrel,
                       float* __restrict__ out){
    __shared__ float s0[192], s1[192], s2[192];
    int j = threadIdx.x;                            // 64 threads
    float* pad = out + OFF_I + (size_t)NI*192;
    #pragma unroll
    for (int i = 0; i < 3; i++) pad[i*64 + j] = 0.f;
    float* out_rela = out + OFF_RELA;
    #pragma unroll
    for (int i = 0; i < 3; i++) s0[i*64+j] = rel_emb[i*64+j];
    __syncthreads();
    #pragma unroll
    for (int i = 0; i < 3; i++){
        float a = 0.f;
        #pragma unroll
        for (int d = 0; d < 64; d++) a += s0[i*64+d]*Wrel[d*64+j];
        s1[i*64+j] = a;
    }
    __syncthreads();
    #pragma unroll
    for (int i = 0; i < 3; i++){
        float a = 0.f;
        #pragma unroll
        for (int d = 0; d < 64; d++) a += s1[i*64+d]*Wrel[4096 + d*64+j];
        s2[i*64+j] = a;
    }
    __syncthreads();
    #pragma unroll
    for (int i = 0; i < 3; i++){
        g_rela[        i*64+j] = s0[i*64+j];
        g_rela[192   + i*64+j] = s1[i*64+j];
        g_rela[384   + i*64+j] = s2[i*64+j];
        out_rela[i*64+j] = (s0[i*64+j] + s1[i*64+j] + s2[i*64+j]) * (1.f/3.f);
    }
}

// ---------------- zero bucket counters ----------------
__global__ __launch_bounds__(256) void k_zero_cnt(){
    int t = blockIdx.x*256 + threadIdx.x;
    if (t < RR*NN) g_cnt[t] = 0;
}

// ---------------- bucket build: per (rel,row) edge list, MLP=8 ----------------
#define EQ8 (EE/8)
__global__ __launch_bounds__(256) void k_bucket(const float* __restrict__ vals,
                                                const int*   __restrict__ rows,
                                                const int*   __restrict__ cols){
    int rel = blockIdx.y;
    int e   = blockIdx.x*256 + threadIdx.x;    // 0 .. EQ8-1
    if (e >= EQ8) return;
    int f[8], row[8], col[8];
    float v[8];
    #pragma unroll
    for (int q = 0; q < 8; q++) f[q] = rel*EE + e + q*EQ8;
    #pragma unroll
    for (int q = 0; q < 8; q++){
        row[q] = __ldg(rows + f[q]);
        col[q] = __ldg(cols + f[q]);
        v[q]   = __ldg(vals + f[q]);
    }
    int pos[8];
    #pragma unroll
    for (int q = 0; q < 8; q++)
        pos[q] = atomicAdd(&g_cnt[rel*NN + row[q]], 1);
    #pragma unroll
    for (int q = 0; q < 8; q++)
        if (pos[q] < CAP)
            g_bkt[((size_t)(rel*NN + row[q]))*CAP + pos[q]] = make_int2(col[q], __float_as_int(v[q]));
}

#define WARP_SUM(x) { _Pragma("unroll") for (int _o = 16; _o; _o >>= 1) x += __shfl_xor_sync(0xffffffffu, x, _o); }

// ---------------- fused layer: gather -> (.*rela)@Wgc -> lrelu -> attn ----------
// K=0: ego/all written.  K=1: final attention fused, writes u/i_emb to out.
// block = 32 nodes = 96 (node,rel) rows, 384 threads
// gather: 12 warps steal rows dynamically (1 warp = 1 row, float2/lane)
template<int K>
__global__ __launch_bounds__(384, 4) void k_layer(const float* __restrict__ Wgc,
                                                  float scale,
                                                  const float* __restrict__ ue,
                                                  const float* __restrict__ ie,
                                                  float* __restrict__ out){
    __shared__ __align__(16) float Ws[64*64];     // 16KB
    __shared__ __align__(16) float Abuf[6528];    // stage: [c*100 + rl] / est: 96x68
    __shared__ __align__(16) float srel[192];
    __shared__ int s_next;
    int tid = threadIdx.x;
    int n0  = blockIdx.x*32;

    if (tid == 0) s_next = 0;
    #pragma unroll
    for (int i = 0; i < 3; i++){
        int idx = i*384 + tid;
        if (idx < 1024) ((float4*)Ws)[idx] = ((const float4*)Wgc)[idx];
    }
    if (tid < 192) srel[tid] = g_rela[K*192 + tid];
    __syncthreads();

    // ---- gather with dynamic row stealing: one warp per row ----
    {
        int lane = tid & 31;
        for (;;){
            int rl;
            if (lane == 0) rl = atomicAdd(&s_next, 1);
            rl = __shfl_sync(0xffffffffu, rl, 0);
            if (rl >= 96) break;
            int nd  = n0 + rl/3;
            int rel = rl - (rl/3)*3;
            int seg = rel*NN + nd;
            int cnt = g_cnt[seg];
            if (cnt > CAP) cnt = CAP;
            const int2* bp = g_bkt + (size_t)seg*CAP;
            float2 acc = make_float2(0.f, 0.f);
            for (int e = 0; e < cnt; e += 4){
                int4 pa = *(const int4*)(bp + e);       // slots >= cnt are (0,0) => no-op
                int4 pb = *(const int4*)(bp + e + 2);
                const float *s0, *s1, *s2, *s3;
                if (K == 0){
                    s0 = (pa.x < NU) ? ue + (size_t)pa.x*64 : ie + (size_t)(pa.x-NU)*64;
                    s1 = (pa.z < NU) ? ue + (size_t)pa.z*64 : ie + (size_t)(pa.z-NU)*64;
                    s2 = (pb.x < NU) ? ue + (size_t)pb.x*64 : ie + (size_t)(pb.x-NU)*64;
                    s3 = (pb.z < NU) ? ue + (size_t)pb.z*64 : ie + (size_t)(pb.z-NU)*64;
                } else {
                    s0 = g_ego + ((size_t)pa.x*3 + rel)*64;
                    s1 = g_ego + ((size_t)pa.z*3 + rel)*64;
                    s2 = g_ego + ((size_t)pb.x*3 + rel)*64;
                    s3 = g_ego + ((size_t)pb.z*3 + rel)*64;
                }
                float2 m0 = *(const float2*)(s0 + lane*2);
                float2 m1 = *(const float2*)(s1 + lane*2);
                float2 m2 = *(const float2*)(s2 + lane*2);
                float2 m3 = *(const float2*)(s3 + lane*2);
                float v0 = __int_as_float(pa.y), v1 = __int_as_float(pa.w);
                float v2 = __int_as_float(pb.y), v3 = __int_as_float(pb.w);
                acc.x = fmaf(m0.x, v0, fmaf(m1.x, v1, fmaf(m2.x, v2, fmaf(m3.x, v3, acc.x))));
                acc.y = fmaf(m0.y, v0, fmaf(m1.y, v1, fmaf(m2.y, v2, fmaf(m3.y, v3, acc.y))));
            }
            // stage A transposed with rela scaling: Abuf[c*100 + rl]
            int c0 = lane*2;
            Abuf[(c0+0)*100 + rl] = acc.x * srel[rel*64 + c0+0];
            Abuf[(c0+1)*100 + rl] = acc.y * srel[rel*64 + c0+1];
        }
    }
    __syncthreads();

    int tx = tid & 15, ty = tid >> 4;      // ty 0..23 (24*4=96 rows), tx*4 cols
    float acc[4][4] = {};
    #pragma unroll
    for (int d = 0; d < 64; d++){
        float4 a = *(const float4*)&Abuf[d*100 + ty*4];
        float4 b = *(const float4*)&Ws[d*64 + tx*4];
        float av[4] = {a.x,a.y,a.z,a.w};
        float bv[4] = {b.x,b.y,b.z,b.w};
        #pragma unroll
        for (int ii = 0; ii < 4; ii++)
            #pragma unroll
            for (int jj = 0; jj < 4; jj++)
                acc[ii][jj] += av[ii]*bv[jj];
    }
    __syncthreads();   // all reads of Abuf done; now reuse as est[96][68]
    #pragma unroll
    for (int ii = 0; ii < 4; ii++){
        float4 o;
        o.x = lrelu(acc[ii][0]); o.y = lrelu(acc[ii][1]);
        o.z = lrelu(acc[ii][2]); o.w = lrelu(acc[ii][3]);
        *(float4*)&Abuf[(ty*4 + ii)*68 + tx*4] = o;
    }
    __syncthreads();

    // attention: 12 warps cover 32 local nodes
    int warp = tid >> 5, lane = tid & 31;
    for (int ln = warp; ln < 32; ln += 12){
        int node = n0 + ln;
        float2 e0 = *(float2*)&Abuf[(3*ln + 0)*68 + lane*2];
        float2 e1 = *(float2*)&Abuf[(3*ln + 1)*68 + lane*2];
        float2 e2 = *(float2*)&Abuf[(3*ln + 2)*68 + lane*2];
        float g00 = e0.x*e0.x + e0.y*e0.y;
        float g01 = e0.x*e1.x + e0.y*e1.y;
        float g02 = e0.x*e2.x + e0.y*e2.y;
        float g11 = e1.x*e1.x + e1.y*e1.y;
        float g12 = e1.x*e2.x + e1.y*e2.y;
        float g22 = e2.x*e2.x + e2.y*e2.y;
        WARP_SUM(g00); WARP_SUM(g01); WARP_SUM(g02);
        WARP_SUM(g11); WARP_SUM(g12); WARP_SUM(g22);
        float G[3][3] = {{g00,g01,g02},{g01,g11,g12},{g02,g12,g22}};
        size_t base = (size_t)node*192 + lane*2;
        float2 al[3];
        if (K == 0){
            const float* ep = (node < NU) ? ue + (size_t)node*64 : ie + (size_t)(node-NU)*64;
            float2 em = *(const float2*)(ep + lane*2);
            #pragma unroll
            for (int r = 0; r < 3; r++){
                float l0 = G[r][0]*scale, l1 = G[r][1]*scale, l2 = G[r][2]*scale;
                float m = fmaxf(l0, fmaxf(l1, l2));
                float w0 = __expf(l0 - m), w1 = __expf(l1 - m), w2 = __expf(l2 - m);
                float inv = 1.f/(w0 + w1 + w2);
                w0 *= inv; w1 *= inv; w2 *= inv;
                float2 o;
                o.x = w0*e0.x + w1*e1.x + w2*e2.x;
                o.y = w0*e0.y + w1*e1.y + w2*e2.y;
                *(float2*)(g_ego + base + r*64) = o;                  // feeds layer-1 gather
                float2 a = make_float2(em.x + o.x, em.y + o.y);       // all = emb + ego
                *(float2*)(g_all + base + r*64) = a;
            }
        } else {
            #pragma unroll
            for (int r = 0; r < 3; r++){
                float l0 = G[r][0]*scale, l1 = G[r][1]*scale, l2 = G[r][2]*scale;
                float m = fmaxf(l0, fmaxf(l1, l2));
                float w0 = __expf(l0 - m), w1 = __expf(l1 - m), w2 = __expf(l2 - m);
                float inv = 1.f/(w0 + w1 + w2);
                w0 *= inv; w1 *= inv; w2 *= inv;
                float2 o;
                o.x = w0*e0.x + w1*e1.x + w2*e2.x;
                o.y = w0*e0.y + w1*e1.y + w2*e2.y;
                float2 a = *(float2*)(g_all + base + r*64);           // all += ego (in regs)
                al[r] = make_float2(a.x + o.x, a.y + o.y);
            }
            // fused final attention (no scale), query = row 2
            float g20 = al[2].x*al[0].x + al[2].y*al[0].y;
            float g21 = al[2].x*al[1].x + al[2].y*al[1].y;
            float g22f = al[2].x*al[2].x + al[2].y*al[2].y;
            WARP_SUM(g20); WARP_SUM(g21); WARP_SUM(g22f);
            float m = fmaxf(g20, fmaxf(g21, g22f));
            float w0 = __expf(g20 - m), w1 = __expf(g21 - m), w2 = __expf(g22f - m);
            float inv = 1.f/(w0 + w1 + w2);
            w0 *= inv; w1 *= inv; w2 *= inv;
            float2 mid;
            mid.x = w0*al[0].x + w1*al[1].x + w2*al[2].x;
            mid.y = w0*al[0].y + w1*al[1].y + w2*al[2].y;
            const float third = 1.f/3.f;
            float* dst = (node < NU) ? out + (size_t)node*192 + lane*2
                                     : out + OFF_I + (size_t)(node-NU)*192 + lane*2;
            *(float2*)(dst)       = make_float2(al[0].x*third, al[0].y*third);
            *(float2*)(dst + 64)  = make_float2(al[1].x*third, al[1].y*third);
            *(float2*)(dst + 128) = make_float2(mid.x*third, mid.y*third);
        }
    }
}

// ---------------- GRU gates + scores ----------------
__global__ __launch_bounds__(256) void k_score(const float* __restrict__ u,
                                               const float* __restrict__ gru_w,
                                               const float* __restrict__ gru_b,
                                               const float* __restrict__ tra,
                                               float* __restrict__ s1,
                                               float* __restrict__ s2){
    __shared__ __align__(16) float Ws[64*64];
    __shared__ __align__(16) float As[64*68];
    __shared__ float red1[64*16];
    __shared__ float red2[64*16];
    int tid = threadIdx.x;
    int u0 = blockIdx.x*64;
    int tx = tid & 15, ty = tid >> 4;
    float ps1[4] = {}, ps2[4] = {};
    for (int r = 0; r < 3; r++){
        if (r) __syncthreads();
        #pragma unroll
        for (int i = 0; i < 4; i++)
            ((float4*)Ws)[tid + i*256] = ((const float4*)(gru_w + r*4096))[tid + i*256];
        #pragma unroll
        for (int i = 0; i < 16; i++){
            int flat = i*256 + tid;
            int ul = flat >> 6, c = flat & 63;
            int user = u0 + ul;
            As[c*68 + ul] = (user < NU) ? u[(size_t)user*192 + r*64 + c] : 0.f;
        }
        __syncthreads();
        float acc[4][4] = {};
        #pragma unroll
        for (int d = 0; d < 64; d++){
            float4 a = *(const float4*)&As[d*68 + ty*4];
            float4 b = *(const float4*)&Ws[d*64 + tx*4];
            float av[4] = {a.x,a.y,a.z,a.w};
            float bv[4] = {b.x,b.y,b.z,b.w};
            #pragma unroll
            for (int ii = 0; ii < 4; ii++)
                #pragma unroll
                for (int jj = 0; jj < 4; jj++)
                    acc[ii][jj] += av[ii]*bv[jj];
        }
        #pragma unroll
        for (int ii = 0; ii < 4; ii++){
            #pragma unroll
            for (int jj = 0; jj < 4; jj++){
                int j = tx*4 + jj;
                float uval = As[j*68 + ty*4 + ii];
                float h = uval * (acc[ii][jj] + __ldg(gru_b + r*64 + j));
                if (r == 2){       // tgt feeds both scores
                    ps1[ii] += h*__ldg(tra + j);
                    ps2[ii] += h*__ldg(tra + 128 + j);
                } else if (r == 0){
                    ps1[ii] += h*__ldg(tra + 64 + j);
                } else {
                    ps2[ii] += h*__ldg(tra + 128 + 64 + j);
                }
            }
        }
    }
    __syncthreads();
    #pragma unroll
    for (int ii = 0; ii < 4; ii++){
        red1[(ty*4+ii)*16 + tx] = ps1[ii];
        red2[(ty*4+ii)*16 + tx] = ps2[ii];
    }
    __syncthreads();
    if (tid < 64){
        float a = 0.f, b = 0.f;
        #pragma unroll
        for (int t = 0; t < 16; t++){ a += red1[tid*16 + t]; b += red2[tid*16 + t]; }
        int user = u0 + tid;
        if (user < NU){ s1[user] = a; s2[user] = b; }
    }
}

extern "C" void kernel_launch(void* const* d_in, const int* in_sizes, int n_in,
                              void* d_out, int out_size){
    const float* user_emb = (const float*)d_in[0];
    const float* item_emb = (const float*)d_in[1];
    const float* rel_emb  = (const float*)d_in[2];
    const float* W_gc     = (const float*)d_in[3];
    const float* W_rel    = (const float*)d_in[4];
    const float* gru_w    = (const float*)d_in[5];
    const float* gru_b    = (const float*)d_in[6];
    const float* tra      = (const float*)d_in[7];
    const float* adj_vals = (const float*)d_in[8];
    const int*   adj_rows = (const int*)  d_in[9];
    const int*   adj_cols = (const int*)  d_in[10];
    float* out = (float*)d_out;

    k_rela<<<1, 64>>>(rel_emb, W_rel, out);
    k_zero_cnt<<<(RR*NN + 255)/256, 256>>>();
    k_bucket<<<dim3((EQ8 + 255)/256, 3), 256>>>(adj_vals, adj_rows, adj_cols);

    const float inv_sqrt = 0.08838834764831845f;  // 1/sqrt(128)
    k_layer<0><<<NN/32, 384>>>(W_gc,        inv_sqrt, user_emb, item_emb, out);
    k_layer<1><<<NN/32, 384>>>(W_gc + 4096, inv_sqrt, user_emb, item_emb, out);
    k_score<<<(NU + 63)/64, 256>>>(out, gru_w, gru_b, tra,
                                   out + OFF_S1, out + OFF_S2);
}

// round 9
// speedup vs baseline: 1.0607x; 1.0607x over previous
#include <cuda_runtime.h>
#include <cuda_bf16.h>
#include <cstdint>

#define NU 70000
#define NI 30000
#define NN 100000   // NU+NI
#define RR 3
#define DD 64
#define EE 1600000
#define CAP 64                 // bucket capacity per (rel,row)

// output layout (f32, flattened tuple)
#define OFF_U   ((size_t)0)
#define OFF_I   ((size_t)NU*192)                    // 13,440,000
#define OFF_RELA (OFF_I + (size_t)(NI+1)*192)       // 19,200,192
#define OFF_S1  (OFF_RELA + 192)                    // 19,200,384
#define OFF_S2  (OFF_S1 + NU)                       // 19,270,384

// -------- scratch (device globals; no allocation allowed) --------
__device__ float g_ego [(size_t)NN*RR*DD];
__device__ float g_all [(size_t)NN*RR*DD];
__device__ float g_rela[3*RR*DD];   // rela[0..2], each 3x64
__device__ int   g_cnt [RR*NN];
__device__ __align__(16) int2 g_bkt[(size_t)RR*NN*CAP];   // zero-init; unwritten slots stay (0, 0.0f)

__device__ __forceinline__ float lrelu(float x){ return x > 0.f ? x : 0.01f*x; }

// ---------------- rela chain + rela_out + i_emb pad row ----------------
__global__ void k_rela(const float* __restrict__ rel_emb,
                       const float* __restrict__ Wrel,
                       float* __restrict__ out){
    __shared__ float s0[192], s1[192], s2[192];
    int j = threadIdx.x;                            // 64 threads
    float* pad = out + OFF_I + (size_t)NI*192;
    #pragma unroll
    for (int i = 0; i < 3; i++) pad[i*64 + j] = 0.f;
    float* out_rela = out + OFF_RELA;
    #pragma unroll
    for (int i = 0; i < 3; i++) s0[i*64+j] = rel_emb[i*64+j];
    __syncthreads();
    #pragma unroll
    for (int i = 0; i < 3; i++){
        float a = 0.f;
        #pragma unroll
        for (int d = 0; d < 64; d++) a += s0[i*64+d]*Wrel[d*64+j];
        s1[i*64+j] = a;
    }
    __syncthreads();
    #pragma unroll
    for (int i = 0; i < 3; i++){
        float a = 0.f;
        #pragma unroll
        for (int d = 0; d < 64; d++) a += s1[i*64+d]*Wrel[4096 + d*64+j];
        s2[i*64+j] = a;
    }
    __syncthreads();
    #pragma unroll
    for (int i = 0; i < 3; i++){
        g_rela[        i*64+j] = s0[i*64+j];
        g_rela[192   + i*64+j] = s1[i*64+j];
        g_rela[384   + i*64+j] = s2[i*64+j];
        out_rela[i*64+j] = (s0[i*64+j] + s1[i*64+j] + s2[i*64+j]) * (1.f/3.f);
    }
}

// ---------------- zero bucket counters ----------------
__global__ __launch_bounds__(256) void k_zero_cnt(){
    int t = blockIdx.x*256 + threadIdx.x;
    if (t < RR*NN) g_cnt[t] = 0;
}

// ---------------- bucket build: per (rel,row) edge list, MLP=8 ----------------
#define EQ8 (EE/8)
__global__ __launch_bounds__(256) void k_bucket(const float* __restrict__ vals,
                                                const int*   __restrict__ rows,
                                                const int*   __restrict__ cols){
    int rel = blockIdx.y;
    int e   = blockIdx.x*256 + threadIdx.x;    // 0 .. EQ8-1
    if (e >= EQ8) return;
    int f[8], row[8], col[8];
    float v[8];
    #pragma unroll
    for (int q = 0; q < 8; q++) f[q] = rel*EE + e + q*EQ8;
    #pragma unroll
    for (int q = 0; q < 8; q++){
        row[q] = __ldg(rows + f[q]);
        col[q] = __ldg(cols + f[q]);
        v[q]   = __ldg(vals + f[q]);
    }
    int pos[8];
    #pragma unroll
    for (int q = 0; q < 8; q++)
        pos[q] = atomicAdd(&g_cnt[rel*NN + row[q]], 1);
    #pragma unroll
    for (int q = 0; q < 8; q++)
        if (pos[q] < CAP)
            g_bkt[((size_t)(rel*NN + row[q]))*CAP + pos[q]] = make_int2(col[q], __float_as_int(v[q]));
}

#define WARP_SUM(x) { _Pragma("unroll") for (int _o = 16; _o; _o >>= 1) x += __shfl_xor_sync(0xffffffffu, x, _o); }

// ---------------- fused layer: gather -> (.*rela)@Wgc -> lrelu -> attn ----------
// K=0: ego/all written.  K=1: final attention fused, writes u/i_emb to out.
// block = 32 nodes = 96 (node,rel) rows, 384 threads
// gather: round-6 engine (16-lane groups, float4/lane, 4 edges in flight)
//         + dynamic stealing at 2-rows-per-warp granularity
template<int K>
__global__ __launch_bounds__(384, 4) void k_layer(const float* __restrict__ Wgc,
                                                  float scale,
                                                  const float* __restrict__ ue,
                                                  const float* __restrict__ ie,
                                                  float* __restrict__ out){
    __shared__ __align__(16) float Ws[64*64];     // 16KB
    __shared__ __align__(16) float Abuf[6528];    // stage: [c*100 + rl] / est: 96x68
    __shared__ __align__(16) float srel[192];
    __shared__ int s_next;
    int tid = threadIdx.x;
    int n0  = blockIdx.x*32;

    if (tid == 0) s_next = 0;
    #pragma unroll
    for (int i = 0; i < 3; i++){
        int idx = i*384 + tid;
        if (idx < 1024) ((float4*)Ws)[idx] = ((const float4*)Wgc)[idx];
    }
    if (tid < 192) srel[tid] = g_rela[K*192 + tid];
    __syncthreads();

    // ---- gather: each warp steals 2 rows at a time; 16-lane group per row ----
    {
        int lane = tid & 31;
        int half = lane >> 4;         // 0: lanes 0-15, 1: lanes 16-31
        int hlane = lane & 15;
        for (;;){
            int base;
            if (lane == 0) base = atomicAdd(&s_next, 2);
            base = __shfl_sync(0xffffffffu, base, 0);
            if (base >= 96) break;
            int rl  = base + half;    // base even, 96 even => rl < 96
            int nd  = n0 + rl/3;
            int rel = rl - (rl/3)*3;
            int seg = rel*NN + nd;
            int cnt = g_cnt[seg];
            if (cnt > CAP) cnt = CAP;
            const int2* bp = g_bkt + (size_t)seg*CAP;
            float4 acc = make_float4(0.f, 0.f, 0.f, 0.f);
            for (int e = 0; e < cnt; e += 4){
                int4 pa = *(const int4*)(bp + e);       // slots >= cnt are (0,0) => no-op
                int4 pb = *(const int4*)(bp + e + 2);
                const float *s0, *s1, *s2, *s3;
                if (K == 0){
                    s0 = (pa.x < NU) ? ue + (size_t)pa.x*64 : ie + (size_t)(pa.x-NU)*64;
                    s1 = (pa.z < NU) ? ue + (size_t)pa.z*64 : ie + (size_t)(pa.z-NU)*64;
                    s2 = (pb.x < NU) ? ue + (size_t)pb.x*64 : ie + (size_t)(pb.x-NU)*64;
                    s3 = (pb.z < NU) ? ue + (size_t)pb.z*64 : ie + (size_t)(pb.z-NU)*64;
                } else {
                    s0 = g_ego + ((size_t)pa.x*3 + rel)*64;
                    s1 = g_ego + ((size_t)pa.z*3 + rel)*64;
                    s2 = g_ego + ((size_t)pb.x*3 + rel)*64;
                    s3 = g_ego + ((size_t)pb.z*3 + rel)*64;
                }
                float4 m0 = *(const float4*)(s0 + hlane*4);
                float4 m1 = *(const float4*)(s1 + hlane*4);
                float4 m2 = *(const float4*)(s2 + hlane*4);
                float4 m3 = *(const float4*)(s3 + hlane*4);
                float v0 = __int_as_float(pa.y), v1 = __int_as_float(pa.w);
                float v2 = __int_as_float(pb.y), v3 = __int_as_float(pb.w);
                acc.x = fmaf(m0.x, v0, fmaf(m1.x, v1, fmaf(m2.x, v2, fmaf(m3.x, v3, acc.x))));
                acc.y = fmaf(m0.y, v0, fmaf(m1.y, v1, fmaf(m2.y, v2, fmaf(m3.y, v3, acc.y))));
                acc.z = fmaf(m0.z, v0, fmaf(m1.z, v1, fmaf(m2.z, v2, fmaf(m3.z, v3, acc.z))));
                acc.w = fmaf(m0.w, v0, fmaf(m1.w, v1, fmaf(m2.w, v2, fmaf(m3.w, v3, acc.w))));
            }
            // stage A transposed with rela scaling: Abuf[c*100 + rl]
            int c0 = hlane*4;
            const float* sr = srel + rel*64 + c0;
            Abuf[(c0+0)*100 + rl] = acc.x * sr[0];
            Abuf[(c0+1)*100 + rl] = acc.y * sr[1];
            Abuf[(c0+2)*100 + rl] = acc.z * sr[2];
            Abuf[(c0+3)*100 + rl] = acc.w * sr[3];
        }
    }
    __syncthreads();

    int tx = tid & 15, ty = tid >> 4;      // ty 0..23 (24*4=96 rows), tx*4 cols
    float acc[4][4] = {};
    #pragma unroll
    for (int d = 0; d < 64; d++){
        float4 a = *(const float4*)&Abuf[d*100 + ty*4];
        float4 b = *(const float4*)&Ws[d*64 + tx*4];
        float av[4] = {a.x,a.y,a.z,a.w};
        float bv[4] = {b.x,b.y,b.z,b.w};
        #pragma unroll
        for (int ii = 0; ii < 4; ii++)
            #pragma unroll
            for (int jj = 0; jj < 4; jj++)
                acc[ii][jj] += av[ii]*bv[jj];
    }
    __syncthreads();   // all reads of Abuf done; now reuse as est[96][68]
    #pragma unroll
    for (int ii = 0; ii < 4; ii++){
        float4 o;
        o.x = lrelu(acc[ii][0]); o.y = lrelu(acc[ii][1]);
        o.z = lrelu(acc[ii][2]); o.w = lrelu(acc[ii][3]);
        *(float4*)&Abuf[(ty*4 + ii)*68 + tx*4] = o;
    }
    __syncthreads();

    // attention: 12 warps cover 32 local nodes
    int warp = tid >> 5, lane = tid & 31;
    for (int ln = warp; ln < 32; ln += 12){
        int node = n0 + ln;
        float2 e0 = *(float2*)&Abuf[(3*ln + 0)*68 + lane*2];
        float2 e1 = *(float2*)&Abuf[(3*ln + 1)*68 + lane*2];
        float2 e2 = *(float2*)&Abuf[(3*ln + 2)*68 + lane*2];
        float g00 = e0.x*e0.x + e0.y*e0.y;
        float g01 = e0.x*e1.x + e0.y*e1.y;
        float g02 = e0.x*e2.x + e0.y*e2.y;
        float g11 = e1.x*e1.x + e1.y*e1.y;
        float g12 = e1.x*e2.x + e1.y*e2.y;
        float g22 = e2.x*e2.x + e2.y*e2.y;
        WARP_SUM(g00); WARP_SUM(g01); WARP_SUM(g02);
        WARP_SUM(g11); WARP_SUM(g12); WARP_SUM(g22);
        float G[3][3] = {{g00,g01,g02},{g01,g11,g12},{g02,g12,g22}};
        size_t base = (size_t)node*192 + lane*2;
        float2 al[3];
        if (K == 0){
            const float* ep = (node < NU) ? ue + (size_t)node*64 : ie + (size_t)(node-NU)*64;
            float2 em = *(const float2*)(ep + lane*2);
            #pragma unroll
            for (int r = 0; r < 3; r++){
                float l0 = G[r][0]*scale, l1 = G[r][1]*scale, l2 = G[r][2]*scale;
                float m = fmaxf(l0, fmaxf(l1, l2));
                float w0 = __expf(l0 - m), w1 = __expf(l1 - m), w2 = __expf(l2 - m);
                float inv = 1.f/(w0 + w1 + w2);
                w0 *= inv; w1 *= inv; w2 *= inv;
                float2 o;
                o.x = w0*e0.x + w1*e1.x + w2*e2.x;
                o.y = w0*e0.y + w1*e1.y + w2*e2.y;
                *(float2*)(g_ego + base + r*64) = o;                  // feeds layer-1 gather
                float2 a = make_float2(em.x + o.x, em.y + o.y);       // all = emb + ego
                *(float2*)(g_all + base + r*64) = a;
            }
        } else {
            #pragma unroll
            for (int r = 0; r < 3; r++){
                float l0 = G[r][0]*scale, l1 = G[r][1]*scale, l2 = G[r][2]*scale;
                float m = fmaxf(l0, fmaxf(l1, l2));
                float w0 = __expf(l0 - m), w1 = __expf(l1 - m), w2 = __expf(l2 - m);
                float inv = 1.f/(w0 + w1 + w2);
                w0 *= inv; w1 *= inv; w2 *= inv;
                float2 o;
                o.x = w0*e0.x + w1*e1.x + w2*e2.x;
                o.y = w0*e0.y + w1*e1.y + w2*e2.y;
                float2 a = *(float2*)(g_all + base + r*64);           // all += ego (in regs)
                al[r] = make_float2(a.x + o.x, a.y + o.y);
            }
            // fused final attention (no scale), query = row 2
            float g20 = al[2].x*al[0].x + al[2].y*al[0].y;
            float g21 = al[2].x*al[1].x + al[2].y*al[1].y;
            float g22f = al[2].x*al[2].x + al[2].y*al[2].y;
            WARP_SUM(g20); WARP_SUM(g21); WARP_SUM(g22f);
            float m = fmaxf(g20, fmaxf(g21, g22f));
            float w0 = __expf(g20 - m), w1 = __expf(g21 - m), w2 = __expf(g22f - m);
            float inv = 1.f/(w0 + w1 + w2);
            w0 *= inv; w1 *= inv; w2 *= inv;
            float2 mid;
            mid.x = w0*al[0].x + w1*al[1].x + w2*al[2].x;
            mid.y = w0*al[0].y + w1*al[1].y + w2*al[2].y;
            const float third = 1.f/3.f;
            float* dst = (node < NU) ? out + (size_t)node*192 + lane*2
                                     : out + OFF_I + (size_t)(node-NU)*192 + lane*2;
            *(float2*)(dst)       = make_float2(al[0].x*third, al[0].y*third);
            *(float2*)(dst + 64)  = make_float2(al[1].x*third, al[1].y*third);
            *(float2*)(dst + 128) = make_float2(mid.x*third, mid.y*third);
        }
    }
}

// ---------------- GRU gates + scores ----------------
__global__ __launch_bounds__(256) void k_score(const float* __restrict__ u,
                                               const float* __restrict__ gru_w,
                                               const float* __restrict__ gru_b,
                                               const float* __restrict__ tra,
                                               float* __restrict__ s1,
                                               float* __restrict__ s2){
    __shared__ __align__(16) float Ws[64*64];
    __shared__ __align__(16) float As[64*68];
    __shared__ float red1[64*16];
    __shared__ float red2[64*16];
    int tid = threadIdx.x;
    int u0 = blockIdx.x*64;
    int tx = tid & 15, ty = tid >> 4;
    float ps1[4] = {}, ps2[4] = {};
    for (int r = 0; r < 3; r++){
        if (r) __syncthreads();
        #pragma unroll
        for (int i = 0; i < 4; i++)
            ((float4*)Ws)[tid + i*256] = ((const float4*)(gru_w + r*4096))[tid + i*256];
        #pragma unroll
        for (int i = 0; i < 16; i++){
            int flat = i*256 + tid;
            int ul = flat >> 6, c = flat & 63;
            int user = u0 + ul;
            As[c*68 + ul] = (user < NU) ? u[(size_t)user*192 + r*64 + c] : 0.f;
        }
        __syncthreads();
        float acc[4][4] = {};
        #pragma unroll
        for (int d = 0; d < 64; d++){
            float4 a = *(const float4*)&As[d*68 + ty*4];
            float4 b = *(const float4*)&Ws[d*64 + tx*4];
            float av[4] = {a.x,a.y,a.z,a.w};
            float bv[4] = {b.x,b.y,b.z,b.w};
            #pragma unroll
            for (int ii = 0; ii < 4; ii++)
                #pragma unroll
                for (int jj = 0; jj < 4; jj++)
                    acc[ii][jj] += av[ii]*bv[jj];
        }
        #pragma unroll
        for (int ii = 0; ii < 4; ii++){
            #pragma unroll
            for (int jj = 0; jj < 4; jj++){
                int j = tx*4 + jj;
                float uval = As[j*68 + ty*4 + ii];
                float h = uval * (acc[ii][jj] + __ldg(gru_b + r*64 + j));
                if (r == 2){       // tgt feeds both scores
                    ps1[ii] += h*__ldg(tra + j);
                    ps2[ii] += h*__ldg(tra + 128 + j);
                } else if (r == 0){
                    ps1[ii] += h*__ldg(tra + 64 + j);
                } else {
                    ps2[ii] += h*__ldg(tra + 128 + 64 + j);
                }
            }
        }
    }
    __syncthreads();
    #pragma unroll
    for (int ii = 0; ii < 4; ii++){
        red1[(ty*4+ii)*16 + tx] = ps1[ii];
        red2[(ty*4+ii)*16 + tx] = ps2[ii];
    }
    __syncthreads();
    if (tid < 64){
        float a = 0.f, b = 0.f;
        #pragma unroll
        for (int t = 0; t < 16; t++){ a += red1[tid*16 + t]; b += red2[tid*16 + t]; }
        int user = u0 + tid;
        if (user < NU){ s1[user] = a; s2[user] = b; }
    }
}

extern "C" void kernel_launch(void* const* d_in, const int* in_sizes, int n_in,
                              void* d_out, int out_size){
    const float* user_emb = (const float*)d_in[0];
    const float* item_emb = (const float*)d_in[1];
    const float* rel_emb  = (const float*)d_in[2];
    const float* W_gc     = (const float*)d_in[3];
    const float* W_rel    = (const float*)d_in[4];
    const float* gru_w    = (const float*)d_in[5];
    const float* gru_b    = (const float*)d_in[6];
    const float* tra      = (const float*)d_in[7];
    const float* adj_vals = (const float*)d_in[8];
    const int*   adj_rows = (const int*)  d_in[9];
    const int*   adj_cols = (const int*)  d_in[10];
    float* out = (float*)d_out;

    k_rela<<<1, 64>>>(rel_emb, W_rel, out);
    k_zero_cnt<<<(RR*NN + 255)/256, 256>>>();
    k_bucket<<<dim3((EQ8 + 255)/256, 3), 256>>>(adj_vals, adj_rows, adj_cols);

    const float inv_sqrt = 0.08838834764831845f;  // 1/sqrt(128)
    k_layer<0><<<NN/32, 384>>>(W_gc,        inv_sqrt, user_emb, item_emb, out);
    k_layer<1><<<NN/32, 384>>>(W_gc + 4096, inv_sqrt, user_emb, item_emb, out);
    k_score<<<(NU + 63)/64, 256>>>(out, gru_w, gru_b, tra,
                                   out + OFF_S1, out + OFF_S2);
}

// round 10
// speedup vs baseline: 1.2114x; 1.1421x over previous
#include <cuda_runtime.h>
#include <cuda_bf16.h>
#include <cuda_fp16.h>
#include <cstdint>

#define NU 70000
#define NI 30000
#define NN 100000   // NU+NI
#define RR 3
#define DD 64
#define EE 1600000
#define CAP 64                 // bucket capacity per (rel,row)

// output layout (f32, flattened tuple)
#define OFF_U   ((size_t)0)
#define OFF_I   ((size_t)NU*192)                    // 13,440,000
#define OFF_RELA (OFF_I + (size_t)(NI+1)*192)       // 19,200,192
#define OFF_S1  (OFF_RELA + 192)                    // 19,200,384
#define OFF_S2  (OFF_S1 + NU)                       // 19,270,384

// -------- scratch (device globals; no allocation allowed) --------
__device__ __align__(16) __half g_emb_h[(size_t)NN*DD];        // fp16 node embeddings
__device__ __align__(16) __half g_ego_h[(size_t)NN*RR*DD];     // fp16 ego (layer-1 gather src)
__device__ float g_all [(size_t)NN*RR*DD];
__device__ float g_rela[3*RR*DD];   // rela[0..2], each 3x64
__device__ int   g_cnt [RR*NN];
__device__ __align__(16) int2 g_bkt[(size_t)RR*NN*CAP];   // zero-init; unwritten slots stay (0, 0.0f)

__device__ __forceinline__ float lrelu(float x){ return x > 0.f ? x : 0.01f*x; }

__device__ __forceinline__ float4 h4_to_f4(uint2 u){
    __half2 h0 = *reinterpret_cast<__half2*>(&u.x);
    __half2 h1 = *reinterpret_cast<__half2*>(&u.y);
    float2 f0 = __half22float2(h0);
    float2 f1 = __half22float2(h1);
    return make_float4(f0.x, f0.y, f1.x, f1.y);
}

// ---------------- prep: fp16 compact embedding table ----------------
__global__ __launch_bounds__(256) void k_prep(const float* __restrict__ ue,
                                              const float* __restrict__ ie){
    int t = blockIdx.x*256 + threadIdx.x;        // over NN*16 float4
    if (t >= NN*16) return;
    int n = t >> 4, q = t & 15;
    const float4 v = ((const float4*)(n < NU ? ue + (size_t)n*64 : ie + (size_t)(n-NU)*64))[q];
    __half2 h0 = __floats2half2_rn(v.x, v.y);
    __half2 h1 = __floats2half2_rn(v.z, v.w);
    uint2 o;
    o.x = *reinterpret_cast<uint32_t*>(&h0);
    o.y = *reinterpret_cast<uint32_t*>(&h1);
    *(uint2*)(g_emb_h + (size_t)n*64 + q*4) = o;
}

// ---------------- rela chain + rela_out + i_emb pad row ----------------
__global__ void k_rela(const float* __restrict__ rel_emb,
                       const float* __restrict__ Wrel,
                       float* __restrict__ out){
    __shared__ float s0[192], s1[192], s2[192];
    int j = threadIdx.x;                            // 64 threads
    float* pad = out + OFF_I + (size_t)NI*192;
    #pragma unroll
    for (int i = 0; i < 3; i++) pad[i*64 + j] = 0.f;
    float* out_rela = out + OFF_RELA;
    #pragma unroll
    for (int i = 0; i < 3; i++) s0[i*64+j] = rel_emb[i*64+j];
    __syncthreads();
    #pragma unroll
    for (int i = 0; i < 3; i++){
        float a = 0.f;
        #pragma unroll
        for (int d = 0; d < 64; d++) a += s0[i*64+d]*Wrel[d*64+j];
        s1[i*64+j] = a;
    }
    __syncthreads();
    #pragma unroll
    for (int i = 0; i < 3; i++){
        float a = 0.f;
        #pragma unroll
        for (int d = 0; d < 64; d++) a += s1[i*64+d]*Wrel[4096 + d*64+j];
        s2[i*64+j] = a;
    }
    __syncthreads();
    #pragma unroll
    for (int i = 0; i < 3; i++){
        g_rela[        i*64+j] = s0[i*64+j];
        g_rela[192   + i*64+j] = s1[i*64+j];
        g_rela[384   + i*64+j] = s2[i*64+j];
        out_rela[i*64+j] = (s0[i*64+j] + s1[i*64+j] + s2[i*64+j]) * (1.f/3.f);
    }
}

// ---------------- zero bucket counters ----------------
__global__ __launch_bounds__(256) void k_zero_cnt(){
    int t = blockIdx.x*256 + threadIdx.x;
    if (t < RR*NN) g_cnt[t] = 0;
}

// ---------------- bucket build: per (rel,row) edge list, MLP=8 ----------------
#define EQ8 (EE/8)
__global__ __launch_bounds__(256) void k_bucket(const float* __restrict__ vals,
                                                const int*   __restrict__ rows,
                                                const int*   __restrict__ cols){
    int rel = blockIdx.y;
    int e   = blockIdx.x*256 + threadIdx.x;    // 0 .. EQ8-1
    if (e >= EQ8) return;
    int f[8], row[8], col[8];
    float v[8];
    #pragma unroll
    for (int q = 0; q < 8; q++) f[q] = rel*EE + e + q*EQ8;
    #pragma unroll
    for (int q = 0; q < 8; q++){
        row[q] = __ldg(rows + f[q]);
        col[q] = __ldg(cols + f[q]);
        v[q]   = __ldg(vals + f[q]);
    }
    int pos[8];
    #pragma unroll
    for (int q = 0; q < 8; q++)
        pos[q] = atomicAdd(&g_cnt[rel*NN + row[q]], 1);
    #pragma unroll
    for (int q = 0; q < 8; q++)
        if (pos[q] < CAP)
            g_bkt[((size_t)(rel*NN + row[q]))*CAP + pos[q]] = make_int2(col[q], __float_as_int(v[q]));
}

#define WARP_SUM(x) { _Pragma("unroll") for (int _o = 16; _o; _o >>= 1) x += __shfl_xor_sync(0xffffffffu, x, _o); }

// ---------------- fused layer: gather(fp16) -> (.*rela)@Wgc -> lrelu -> attn ----
// K=0: gathers g_emb_h, writes ego(half)/all(f32).  K=1: gathers g_ego_h,
//      final attention fused, writes u/i_emb to out.
// block = 32 nodes = 96 (node,rel) rows, 384 threads; round-6 static gather
template<int K>
__global__ __launch_bounds__(384, 4) void k_layer(const float* __restrict__ Wgc,
                                                  float scale,
                                                  const float* __restrict__ ue,
                                                  const float* __restrict__ ie,
                                                  float* __restrict__ out){
    __shared__ __align__(16) float Ws[64*64];     // 16KB
    __shared__ __align__(16) float Abuf[6528];    // stage: [c*100 + rl] / est: 96x68
    __shared__ __align__(16) float srel[192];
    int tid = threadIdx.x;
    int n0  = blockIdx.x*32;

    #pragma unroll
    for (int i = 0; i < 3; i++){
        int idx = i*384 + tid;
        if (idx < 1024) ((float4*)Ws)[idx] = ((const float4*)Wgc)[idx];
    }
    if (tid < 192) srel[tid] = g_rela[K*192 + tid];
    __syncthreads();

    // ---- gather: 24 groups of 16 lanes, 4 rows each (static), fp16 rows ----
    {
        int grp  = tid >> 4;            // 0..23
        int lane = tid & 15;
        #pragma unroll
        for (int j = 0; j < 4; j++){
            int rl  = grp*4 + j;        // 0..95
            int nd  = n0 + (rl/3);
            int rel = rl - (rl/3)*3;
            int seg = rel*NN + nd;
            int cnt = g_cnt[seg];
            if (cnt > CAP) cnt = CAP;
            const int2* bp = g_bkt + (size_t)seg*CAP;
            float4 acc = make_float4(0.f,0.f,0.f,0.f);
            for (int e = 0; e < cnt; e += 4){
                int4 pa = *(const int4*)(bp + e);       // slots >= cnt are (0,0) => no-op
                int4 pb = *(const int4*)(bp + e + 2);
                const __half *s0, *s1, *s2, *s3;
                if (K == 0){
                    s0 = g_emb_h + (size_t)pa.x*64;
                    s1 = g_emb_h + (size_t)pa.z*64;
                    s2 = g_emb_h + (size_t)pb.x*64;
                    s3 = g_emb_h + (size_t)pb.z*64;
                } else {
                    s0 = g_ego_h + ((size_t)pa.x*3 + rel)*64;
                    s1 = g_ego_h + ((size_t)pa.z*3 + rel)*64;
                    s2 = g_ego_h + ((size_t)pb.x*3 + rel)*64;
                    s3 = g_ego_h + ((size_t)pb.z*3 + rel)*64;
                }
                uint2 q0 = *(const uint2*)(s0 + lane*4);
                uint2 q1 = *(const uint2*)(s1 + lane*4);
                uint2 q2 = *(const uint2*)(s2 + lane*4);
                uint2 q3 = *(const uint2*)(s3 + lane*4);
                float4 m0 = h4_to_f4(q0);
                float4 m1 = h4_to_f4(q1);
                float4 m2 = h4_to_f4(q2);
                float4 m3 = h4_to_f4(q3);
                float v0 = __int_as_float(pa.y), v1 = __int_as_float(pa.w);
                float v2 = __int_as_float(pb.y), v3 = __int_as_float(pb.w);
                acc.x = fmaf(m0.x, v0, fmaf(m1.x, v1, fmaf(m2.x, v2, fmaf(m3.x, v3, acc.x))));
                acc.y = fmaf(m0.y, v0, fmaf(m1.y, v1, fmaf(m2.y, v2, fmaf(m3.y, v3, acc.y))));
                acc.z = fmaf(m0.z, v0, fmaf(m1.z, v1, fmaf(m2.z, v2, fmaf(m3.z, v3, acc.z))));
                acc.w = fmaf(m0.w, v0, fmaf(m1.w, v1, fmaf(m2.w, v2, fmaf(m3.w, v3, acc.w))));
            }
            // stage A transposed with rela scaling: Abuf[c*100 + rl]
            int c0 = lane*4;
            const float* sr = srel + rel*64 + c0;
            Abuf[(c0+0)*100 + rl] = acc.x * sr[0];
            Abuf[(c0+1)*100 + rl] = acc.y * sr[1];
            Abuf[(c0+2)*100 + rl] = acc.z * sr[2];
            Abuf[(c0+3)*100 + rl] = acc.w * sr[3];
        }
    }
    __syncthreads();

    int tx = tid & 15, ty = tid >> 4;      // ty 0..23 (24*4=96 rows), tx*4 cols
    float acc[4][4] = {};
    #pragma unroll
    for (int d = 0; d < 64; d++){
        float4 a = *(const float4*)&Abuf[d*100 + ty*4];
        float4 b = *(const float4*)&Ws[d*64 + tx*4];
        float av[4] = {a.x,a.y,a.z,a.w};
        float bv[4] = {b.x,b.y,b.z,b.w};
        #pragma unroll
        for (int ii = 0; ii < 4; ii++)
            #pragma unroll
            for (int jj = 0; jj < 4; jj++)
                acc[ii][jj] += av[ii]*bv[jj];
    }
    __syncthreads();   // all reads of Abuf done; now reuse as est[96][68]
    #pragma unroll
    for (int ii = 0; ii < 4; ii++){
        float4 o;
        o.x = lrelu(acc[ii][0]); o.y = lrelu(acc[ii][1]);
        o.z = lrelu(acc[ii][2]); o.w = lrelu(acc[ii][3]);
        *(float4*)&Abuf[(ty*4 + ii)*68 + tx*4] = o;
    }
    __syncthreads();

    // attention: 12 warps cover 32 local nodes
    int warp = tid >> 5, lane = tid & 31;
    for (int ln = warp; ln < 32; ln += 12){
        int node = n0 + ln;
        float2 e0 = *(float2*)&Abuf[(3*ln + 0)*68 + lane*2];
        float2 e1 = *(float2*)&Abuf[(3*ln + 1)*68 + lane*2];
        float2 e2 = *(float2*)&Abuf[(3*ln + 2)*68 + lane*2];
        float g00 = e0.x*e0.x + e0.y*e0.y;
        float g01 = e0.x*e1.x + e0.y*e1.y;
        float g02 = e0.x*e2.x + e0.y*e2.y;
        float g11 = e1.x*e1.x + e1.y*e1.y;
        float g12 = e1.x*e2.x + e1.y*e2.y;
        float g22 = e2.x*e2.x + e2.y*e2.y;
        WARP_SUM(g00); WARP_SUM(g01); WARP_SUM(g02);
        WARP_SUM(g11); WARP_SUM(g12); WARP_SUM(g22);
        float G[3][3] = {{g00,g01,g02},{g01,g11,g12},{g02,g12,g22}};
        size_t base = (size_t)node*192 + lane*2;
        float2 al[3];
        if (K == 0){
            const float* ep = (node < NU) ? ue + (size_t)node*64 : ie + (size_t)(node-NU)*64;
            float2 em = *(const float2*)(ep + lane*2);
            #pragma unroll
            for (int r = 0; r < 3; r++){
                float l0 = G[r][0]*scale, l1 = G[r][1]*scale, l2 = G[r][2]*scale;
                float m = fmaxf(l0, fmaxf(l1, l2));
                float w0 = __expf(l0 - m), w1 = __expf(l1 - m), w2 = __expf(l2 - m);
                float inv = 1.f/(w0 + w1 + w2);
                w0 *= inv; w1 *= inv; w2 *= inv;
                float2 o;
                o.x = w0*e0.x + w1*e1.x + w2*e2.x;
                o.y = w0*e0.y + w1*e1.y + w2*e2.y;
                __half2 hv = __floats2half2_rn(o.x, o.y);             // feeds layer-1 gather
                *(__half2*)(g_ego_h + base + r*64) = hv;
                float2 a = make_float2(em.x + o.x, em.y + o.y);       // all = emb + ego (f32)
                *(float2*)(g_all + base + r*64) = a;
            }
        } else {
            #pragma unroll
            for (int r = 0; r < 3; r++){
                float l0 = G[r][0]*scale, l1 = G[r][1]*scale, l2 = G[r][2]*scale;
                float m = fmaxf(l0, fmaxf(l1, l2));
                float w0 = __expf(l0 - m), w1 = __expf(l1 - m), w2 = __expf(l2 - m);
                float inv = 1.f/(w0 + w1 + w2);
                w0 *= inv; w1 *= inv; w2 *= inv;
                float2 o;
                o.x = w0*e0.x + w1*e1.x + w2*e2.x;
                o.y = w0*e0.y + w1*e1.y + w2*e2.y;
                float2 a = *(float2*)(g_all + base + r*64);           // all += ego (in regs)
                al[r] = make_float2(a.x + o.x, a.y + o.y);
            }
            // fused final attention (no scale), query = row 2
            float g20 = al[2].x*al[0].x + al[2].y*al[0].y;
            float g21 = al[2].x*al[1].x + al[2].y*al[1].y;
            float g22f = al[2].x*al[2].x + al[2].y*al[2].y;
            WARP_SUM(g20); WARP_SUM(g21); WARP_SUM(g22f);
            float m = fmaxf(g20, fmaxf(g21, g22f));
            float w0 = __expf(g20 - m), w1 = __expf(g21 - m), w2 = __expf(g22f - m);
            float inv = 1.f/(w0 + w1 + w2);
            w0 *= inv; w1 *= inv; w2 *= inv;
            float2 mid;
            mid.x = w0*al[0].x + w1*al[1].x + w2*al[2].x;
            mid.y = w0*al[0].y + w1*al[1].y + w2*al[2].y;
            const float third = 1.f/3.f;
            float* dst = (node < NU) ? out + (size_t)node*192 + lane*2
                                     : out + OFF_I + (size_t)(node-NU)*192 + lane*2;
            *(float2*)(dst)       = make_float2(al[0].x*third, al[0].y*third);
            *(float2*)(dst + 64)  = make_float2(al[1].x*third, al[1].y*third);
            *(float2*)(dst + 128) = make_float2(mid.x*third, mid.y*third);
        }
    }
}

// ---------------- GRU gates + scores ----------------
__global__ __launch_bounds__(256) void k_score(const float* __restrict__ u,
                                               const float* __restrict__ gru_w,
                                               const float* __restrict__ gru_b,
                                               const float* __restrict__ tra,
                                               float* __restrict__ s1,
                                               float* __restrict__ s2){
    __shared__ __align__(16) float Ws[64*64];
    __shared__ __align__(16) float As[64*68];
    __shared__ float red1[64*16];
    __shared__ float red2[64*16];
    int tid = threadIdx.x;
    int u0 = blockIdx.x*64;
    int tx = tid & 15, ty = tid >> 4;
    float ps1[4] = {}, ps2[4] = {};
    for (int r = 0; r < 3; r++){
        if (r) __syncthreads();
        #pragma unroll
        for (int i = 0; i < 4; i++)
            ((float4*)Ws)[tid + i*256] = ((const float4*)(gru_w + r*4096))[tid + i*256];
        #pragma unroll
        for (int i = 0; i < 16; i++){
            int flat = i*256 + tid;
            int ul = flat >> 6, c = flat & 63;
            int user = u0 + ul;
            As[c*68 + ul] = (user < NU) ? u[(size_t)user*192 + r*64 + c] : 0.f;
        }
        __syncthreads();
        float acc[4][4] = {};
        #pragma unroll
        for (int d = 0; d < 64; d++){
            float4 a = *(const float4*)&As[d*68 + ty*4];
            float4 b = *(const float4*)&Ws[d*64 + tx*4];
            float av[4] = {a.x,a.y,a.z,a.w};
            float bv[4] = {b.x,b.y,b.z,b.w};
            #pragma unroll
            for (int ii = 0; ii < 4; ii++)
                #pragma unroll
                for (int jj = 0; jj < 4; jj++)
                    acc[ii][jj] += av[ii]*bv[jj];
        }
        #pragma unroll
        for (int ii = 0; ii < 4; ii++){
            #pragma unroll
            for (int jj = 0; jj < 4; jj++){
                int j = tx*4 + jj;
                float uval = As[j*68 + ty*4 + ii];
                float h = uval * (acc[ii][jj] + __ldg(gru_b + r*64 + j));
                if (r == 2){       // tgt feeds both scores
                    ps1[ii] += h*__ldg(tra + j);
                    ps2[ii] += h*__ldg(tra + 128 + j);
                } else if (r == 0){
                    ps1[ii] += h*__ldg(tra + 64 + j);
                } else {
                    ps2[ii] += h*__ldg(tra + 128 + 64 + j);
                }
            }
        }
    }
    __syncthreads();
    #pragma unroll
    for (int ii = 0; ii < 4; ii++){
        red1[(ty*4+ii)*16 + tx] = ps1[ii];
        red2[(ty*4+ii)*16 + tx] = ps2[ii];
    }
    __syncthreads();
    if (tid < 64){
        float a = 0.f, b = 0.f;
        #pragma unroll
        for (int t = 0; t < 16; t++){ a += red1[tid*16 + t]; b += red2[tid*16 + t]; }
        int user = u0 + tid;
        if (user < NU){ s1[user] = a; s2[user] = b; }
    }
}

extern "C" void kernel_launch(void* const* d_in, const int* in_sizes, int n_in,
                              void* d_out, int out_size){
    const float* user_emb = (const float*)d_in[0];
    const float* item_emb = (const float*)d_in[1];
    const float* rel_emb  = (const float*)d_in[2];
    const float* W_gc     = (const float*)d_in[3];
    const float* W_rel    = (const float*)d_in[4];
    const float* gru_w    = (const float*)d_in[5];
    const float* gru_b    = (const float*)d_in[6];
    const float* tra      = (const float*)d_in[7];
    const float* adj_vals = (const float*)d_in[8];
    const int*   adj_rows = (const int*)  d_in[9];
    const int*   adj_cols = (const int*)  d_in[10];
    float* out = (float*)d_out;

    k_prep<<<(NN*16 + 255)/256, 256>>>(user_emb, item_emb);
    k_rela<<<1, 64>>>(rel_emb, W_rel, out);
    k_zero_cnt<<<(RR*NN + 255)/256, 256>>>();
    k_bucket<<<dim3((EQ8 + 255)/256, 3), 256>>>(adj_vals, adj_rows, adj_cols);

    const float inv_sqrt = 0.08838834764831845f;  // 1/sqrt(128)
    k_layer<0><<<NN/32, 384>>>(W_gc,        inv_sqrt, user_emb, item_emb, out);
    k_layer<1><<<NN/32, 384>>>(W_gc + 4096, inv_sqrt, user_emb, item_emb, out);
    k_score<<<(NU + 63)/64, 256>>>(out, gru_w, gru_b, tra,
                                   out + OFF_S1, out + OFF_S2);
}